// round 16
// baseline (speedup 1.0000x reference)
#include <cuda_runtime.h>
#include <cstdint>

#define B_  4
#define S_  2048
#define D_  1024
#define H_  16
#define DK_ 64
#define M_  (B_ * S_)                    // 8192
#define QKV_ELEMS (B_ * H_ * S_ * DK_)   // 8388608

// Scratch (device globals; no runtime allocation)
__device__ float g_Q[QKV_ELEMS];
__device__ float g_Khi[QKV_ELEMS];       // [bh][kv][d]  tf32-hi
__device__ float g_Klo[QKV_ELEMS];       // [bh][kv][d]  residual
__device__ float g_Vhi[QKV_ELEMS];       // [bh][d][kv]  (pre-transposed)
__device__ float g_Vlo[QKV_ELEMS];
__device__ float g_O[QKV_ELEMS];
__device__ float g_WThi[3 * D_ * D_];    // tf32-hi of W^T for Q,K,V: [z][j][d]
__device__ float g_WTlo[3 * D_ * D_];
__device__ float g_WoThi[D_ * D_];       // tf32-hi of Wo^T: [n][j]
__device__ float g_WoTlo[D_ * D_];

// ---------------------------------------------------------------------------
// Helpers (base-ISA only: mma.sync + cp.async)
// ---------------------------------------------------------------------------
__device__ __forceinline__ uint32_t smem_u32(const void* p) {
    uint32_t a;
    asm("{ .reg .u64 t; cvta.to.shared.u64 t, %1; cvt.u32.u64 %0, t; }"
        : "=r"(a) : "l"(p));
    return a;
}
__device__ __forceinline__ uint32_t cvt_tf32(float v) {
    uint32_t r;
    asm("cvt.rna.tf32.f32 %0, %1;" : "=r"(r) : "f"(v));
    return r;
}
// hi via cvt.rna; lo passed as raw fp32 bits (HMMA truncates low mantissa)
__device__ __forceinline__ void split2(float v, uint32_t& hi, uint32_t& lo) {
    hi = cvt_tf32(v);
    lo = __float_as_uint(v - __uint_as_float(hi));
}
// D += A*B, m16n8k8 tf32
__device__ __forceinline__ void mma8(float* c,
                                     uint32_t a0, uint32_t a1, uint32_t a2, uint32_t a3,
                                     uint32_t b0, uint32_t b1) {
    asm volatile(
        "mma.sync.aligned.m16n8k8.row.col.f32.tf32.tf32.f32 "
        "{%0,%1,%2,%3}, {%4,%5,%6,%7}, {%8,%9}, {%0,%1,%2,%3};"
        : "+f"(c[0]), "+f"(c[1]), "+f"(c[2]), "+f"(c[3])
        : "r"(a0), "r"(a1), "r"(a2), "r"(a3), "r"(b0), "r"(b1));
}
__device__ __forceinline__ void cp16(uint32_t saddr, const void* gptr) {
    asm volatile("cp.async.cg.shared.global [%0], [%1], 16;"
                 :: "r"(saddr), "l"(gptr) : "memory");
}
#define CP_COMMIT() asm volatile("cp.async.commit_group;" ::: "memory")
#define CP_WAIT(n)  asm volatile("cp.async.wait_group %0;" :: "n"(n) : "memory")

// ---------------------------------------------------------------------------
// Weight transposes + tf32 hi/lo pre-split (once per launch)
// ---------------------------------------------------------------------------
__global__ void transpose_qkv(const float* __restrict__ Wq,
                              const float* __restrict__ Wk,
                              const float* __restrict__ Wv)
{
    __shared__ float t[32][33];
    const int z = blockIdx.z >> 4;
    const int h = blockIdx.z & 15;
    const float* in = (z == 0 ? Wq : z == 1 ? Wk : Wv) + (size_t)h * D_ * DK_;
    const int j0 = blockIdx.x * 32;
    const int d0 = blockIdx.y * 32;
    const int tx = threadIdx.x, ty = threadIdx.y;
#pragma unroll
    for (int q = 0; q < 4; q++)
        t[ty + 8 * q][tx] = in[(size_t)(d0 + ty + 8 * q) * DK_ + j0 + tx];
    __syncthreads();
    const size_t ob = (size_t)z * D_ * D_ + (size_t)(h * 64 + j0) * D_ + d0;
#pragma unroll
    for (int q = 0; q < 4; q++) {
        const float v = t[tx][ty + 8 * q];
        const uint32_t hi = cvt_tf32(v);
        g_WThi[ob + (size_t)(ty + 8 * q) * D_ + tx] = __uint_as_float(hi);
        g_WTlo[ob + (size_t)(ty + 8 * q) * D_ + tx] = v - __uint_as_float(hi);
    }
}

__global__ void transpose_wo(const float* __restrict__ Wo)
{
    __shared__ float t[32][33];
    const int n0 = blockIdx.x * 32;
    const int j0 = blockIdx.y * 32;
    const int tx = threadIdx.x, ty = threadIdx.y;
#pragma unroll
    for (int q = 0; q < 4; q++)
        t[ty + 8 * q][tx] = Wo[(size_t)(j0 + ty + 8 * q) * D_ + n0 + tx];
    __syncthreads();
#pragma unroll
    for (int q = 0; q < 4; q++) {
        const float v = t[tx][ty + 8 * q];
        const uint32_t hi = cvt_tf32(v);
        g_WoThi[(size_t)(n0 + ty + 8 * q) * D_ + j0 + tx] = __uint_as_float(hi);
        g_WoTlo[(size_t)(n0 + ty + 8 * q) * D_ + j0 + tx] = v - __uint_as_float(hi);
    }
}

// ---------------------------------------------------------------------------
// GEMM: 128x128x32 CTA tile, 8 warps (4x2), warp tile 32x64, cp.async 2-stage.
// 256 threads, smem 110592 -> 2 CTAs/SM = 16 warps/SM. Low reg pressure
// (~100 regs: 64 accum + 16 live A-frags) so the 128-reg cap is easy.
// B operand pre-split (Bhi/Blo planes).
// ---------------------------------------------------------------------------
#define GPAD 36
#define GEMM_SMEM (2 * 3 * 128 * GPAD * 4)   // 110592 B

__device__ __forceinline__ void gemm_chunkW(const float (*As)[GPAD],
                                            const float (*Bhs)[GPAD],
                                            const float (*Bls)[GPAD],
                                            int wm, int wn, int g, int t,
                                            float c[2][8][4])
{
#pragma unroll
    for (int ks = 0; ks < 4; ks++) {
        const int kc = ks * 8;
        uint32_t ah[2][4], al[2][4];
#pragma unroll
        for (int mf = 0; mf < 2; mf++) {
            const int r = wm * 32 + mf * 16;
            split2(As[r + g][kc + t],          ah[mf][0], al[mf][0]);
            split2(As[r + g + 8][kc + t],      ah[mf][1], al[mf][1]);
            split2(As[r + g][kc + t + 4],      ah[mf][2], al[mf][2]);
            split2(As[r + g + 8][kc + t + 4],  ah[mf][3], al[mf][3]);
        }
#pragma unroll
        for (int nf = 0; nf < 8; nf++) {
            const int n = wn * 64 + nf * 8;
            const uint32_t bh0 = __float_as_uint(Bhs[n + g][kc + t]);
            const uint32_t bh1 = __float_as_uint(Bhs[n + g][kc + t + 4]);
            const uint32_t bl0 = __float_as_uint(Bls[n + g][kc + t]);
            const uint32_t bl1 = __float_as_uint(Bls[n + g][kc + t + 4]);
#pragma unroll
            for (int mf = 0; mf < 2; mf++) {
                mma8(c[mf][nf], ah[mf][0], ah[mf][1], ah[mf][2], ah[mf][3], bh0, bh1);
                mma8(c[mf][nf], ah[mf][0], ah[mf][1], ah[mf][2], ah[mf][3], bl0, bl1);
                mma8(c[mf][nf], al[mf][0], al[mf][1], al[mf][2], al[mf][3], bh0, bh1);
            }
        }
    }
}

// ---------------------------------------------------------------------------
// QKV projection. Epilogue: z=0 -> g_Q (fp32); z=1 -> K split planes [bh][kv][d];
// z=2 -> V split planes TRANSPOSED [bh][d][kv].
// ---------------------------------------------------------------------------
__global__ __launch_bounds__(256, 2) void qkv_mma(
    const float* __restrict__ x,
    const float* __restrict__ bq, const float* __restrict__ bk,
    const float* __restrict__ bv)
{
    extern __shared__ float sm[];
    float (*Asm)[GPAD]  = (float(*)[GPAD])sm;
    float (*Bhsm)[GPAD] = (float(*)[GPAD])(sm + 2 * 128 * GPAD);
    float (*Blsm)[GPAD] = (float(*)[GPAD])(sm + 4 * 128 * GPAD);

    const int tid = threadIdx.x;
    const int wid = tid >> 5;
    const int lane = tid & 31;
    const int g = lane >> 2, t = lane & 3;
    const int wm = wid & 3, wn = wid >> 2;       // 4 x 2 warp grid, tile 32x64
    const int m0 = blockIdx.x * 128;
    const int n0 = blockIdx.y * 128;
    const int z  = blockIdx.z;

    const float* Bth = g_WThi + (size_t)z * D_ * D_;
    const float* Btl = g_WTlo + (size_t)z * D_ * D_;
    const float* bias = (z == 0) ? bq : (z == 1) ? bk : bv;

    const int lr = tid >> 3;          // 0..31 (x4 -> 128 rows)
    const int lc = (tid & 7) * 4;

    const uint32_t aB  = smem_u32(sm);
    const uint32_t bhB = aB + 2 * 128 * GPAD * 4;
    const uint32_t blB = aB + 4 * 128 * GPAD * 4;

#pragma unroll
    for (int i = 0; i < 4; i++) {
        const int r = lr + i * 32;
        cp16(aB  + (uint32_t)(r * GPAD + lc) * 4, &x  [(size_t)(m0 + r) * D_ + lc]);
        cp16(bhB + (uint32_t)(r * GPAD + lc) * 4, &Bth[(size_t)(n0 + r) * D_ + lc]);
        cp16(blB + (uint32_t)(r * GPAD + lc) * 4, &Btl[(size_t)(n0 + r) * D_ + lc]);
    }
    CP_COMMIT();

    float c[2][8][4];
#pragma unroll
    for (int a = 0; a < 2; a++)
#pragma unroll
        for (int b = 0; b < 8; b++)
#pragma unroll
            for (int q = 0; q < 4; q++) c[a][b][q] = 0.0f;

    for (int ch = 0; ch < 32; ch++) {
        const int s = ch & 1;
        if (ch + 1 < 32) {
            const int k0 = (ch + 1) * 32;
            const uint32_t so = (uint32_t)((ch + 1) & 1) * 128 * GPAD * 4;
#pragma unroll
            for (int i = 0; i < 4; i++) {
                const int r = lr + i * 32;
                cp16(aB  + so + (uint32_t)(r * GPAD + lc) * 4,
                     &x  [(size_t)(m0 + r) * D_ + k0 + lc]);
                cp16(bhB + so + (uint32_t)(r * GPAD + lc) * 4,
                     &Bth[(size_t)(n0 + r) * D_ + k0 + lc]);
                cp16(blB + so + (uint32_t)(r * GPAD + lc) * 4,
                     &Btl[(size_t)(n0 + r) * D_ + k0 + lc]);
            }
            CP_COMMIT();
            CP_WAIT(1);
        } else {
            CP_WAIT(0);
        }
        __syncthreads();
        gemm_chunkW(&Asm[s * 128], &Bhsm[s * 128], &Blsm[s * 128], wm, wn, g, t, c);
        __syncthreads();
    }

#pragma unroll
    for (int mf = 0; mf < 2; mf++) {
#pragma unroll
        for (int nf = 0; nf < 8; nf++) {
            const int j = n0 + wn * 64 + nf * 8 + 2 * t;
            const int head = j >> 6, kin = j & 63;
            const float bz0 = bias[j], bz1 = bias[j + 1];
#pragma unroll
            for (int rr = 0; rr < 2; rr++) {
                const int m = m0 + wm * 32 + mf * 16 + g + rr * 8;
                const int b = m >> 11, sidx = m & 2047;
                const int bh = b * H_ + head;
                const float v0 = c[mf][nf][rr * 2] + bz0;
                const float v1 = c[mf][nf][rr * 2 + 1] + bz1;
                if (z == 0) {
                    float* p = g_Q + ((size_t)bh * S_ + sidx) * DK_ + kin;
                    *(float2*)p = make_float2(v0, v1);
                } else if (z == 1) {
                    uint32_t h0, l0, h1, l1;
                    split2(v0, h0, l0); split2(v1, h1, l1);
                    const size_t p = ((size_t)bh * S_ + sidx) * DK_ + kin;
                    *(float2*)&g_Khi[p] = make_float2(__uint_as_float(h0),
                                                      __uint_as_float(h1));
                    *(float2*)&g_Klo[p] = make_float2(__uint_as_float(l0),
                                                      __uint_as_float(l1));
                } else {
                    uint32_t h0, l0, h1, l1;
                    split2(v0, h0, l0); split2(v1, h1, l1);
                    const size_t p = ((size_t)bh * DK_ + kin) * S_ + sidx;  // [bh][d][kv]
                    g_Vhi[p]      = __uint_as_float(h0);
                    g_Vlo[p]      = __uint_as_float(l0);
                    g_Vhi[p + S_] = __uint_as_float(h1);
                    g_Vlo[p + S_] = __uint_as_float(l1);
                }
            }
        }
    }
}

// ---------------------------------------------------------------------------
// Output projection
// ---------------------------------------------------------------------------
__global__ __launch_bounds__(256, 2) void out_mma(
    const float* __restrict__ bo, float* __restrict__ out)
{
    extern __shared__ float sm[];
    float (*Asm)[GPAD]  = (float(*)[GPAD])sm;
    float (*Bhsm)[GPAD] = (float(*)[GPAD])(sm + 2 * 128 * GPAD);
    float (*Blsm)[GPAD] = (float(*)[GPAD])(sm + 4 * 128 * GPAD);

    const int tid = threadIdx.x;
    const int wid = tid >> 5;
    const int lane = tid & 31;
    const int g = lane >> 2, t = lane & 3;
    const int wm = wid & 3, wn = wid >> 2;
    const int m0 = blockIdx.x * 128;
    const int n0 = blockIdx.y * 128;
    const int bb = m0 >> 11;
    const int sbase = m0 & 2047;

    const int lr = tid >> 3;
    const int lc = (tid & 7) * 4;

    const uint32_t aB  = smem_u32(sm);
    const uint32_t bhB = aB + 2 * 128 * GPAD * 4;
    const uint32_t blB = aB + 4 * 128 * GPAD * 4;

#pragma unroll
    for (int i = 0; i < 4; i++) {
        const int r = lr + i * 32;
        const float* src = g_O + ((size_t)(bb * H_) * S_ + sbase + r) * DK_ + lc;
        cp16(aB  + (uint32_t)(r * GPAD + lc) * 4, src);
        cp16(bhB + (uint32_t)(r * GPAD + lc) * 4, &g_WoThi[(size_t)(n0 + r) * D_ + lc]);
        cp16(blB + (uint32_t)(r * GPAD + lc) * 4, &g_WoTlo[(size_t)(n0 + r) * D_ + lc]);
    }
    CP_COMMIT();

    float c[2][8][4];
#pragma unroll
    for (int a = 0; a < 2; a++)
#pragma unroll
        for (int b = 0; b < 8; b++)
#pragma unroll
            for (int q = 0; q < 4; q++) c[a][b][q] = 0.0f;

    for (int ch = 0; ch < 32; ch++) {
        const int s = ch & 1;
        if (ch + 1 < 32) {
            const int k0 = (ch + 1) * 32;
            const int head = k0 >> 6, kin = k0 & 63;
            const uint32_t so = (uint32_t)((ch + 1) & 1) * 128 * GPAD * 4;
#pragma unroll
            for (int i = 0; i < 4; i++) {
                const int r = lr + i * 32;
                const float* src = g_O +
                    ((size_t)(bb * H_ + head) * S_ + sbase + r) * DK_ + kin + lc;
                cp16(aB  + so + (uint32_t)(r * GPAD + lc) * 4, src);
                cp16(bhB + so + (uint32_t)(r * GPAD + lc) * 4,
                     &g_WoThi[(size_t)(n0 + r) * D_ + k0 + lc]);
                cp16(blB + so + (uint32_t)(r * GPAD + lc) * 4,
                     &g_WoTlo[(size_t)(n0 + r) * D_ + k0 + lc]);
            }
            CP_COMMIT();
            CP_WAIT(1);
        } else {
            CP_WAIT(0);
        }
        __syncthreads();
        gemm_chunkW(&Asm[s * 128], &Bhsm[s * 128], &Blsm[s * 128], wm, wn, g, t, c);
        __syncthreads();
    }

#pragma unroll
    for (int mf = 0; mf < 2; mf++) {
#pragma unroll
        for (int nf = 0; nf < 8; nf++) {
            const int j = n0 + wn * 64 + nf * 8 + 2 * t;
            const float bz0 = bo[j], bz1 = bo[j + 1];
#pragma unroll
            for (int rr = 0; rr < 2; rr++) {
                const int m = m0 + wm * 32 + mf * 16 + g + rr * 8;
                *(float2*)&out[(size_t)m * D_ + j] =
                    make_float2(c[mf][nf][rr * 2] + bz0, c[mf][nf][rr * 2 + 1] + bz1);
            }
        }
    }
}

// ---------------------------------------------------------------------------
// Causal flash attention v5 (R13, proven 672us — UNCHANGED): pre-split K/V
// planes streamed via cp.async, double-buffered. 256 threads, q-tile 128,
// kv-tile 64.
// ---------------------------------------------------------------------------
#define APAD 68
#define PLANE_B (64 * APAD * 4)              // 17408 B per plane
#define STAGE_B (4 * PLANE_B)                // 69632 B per stage
#define ATTN_SMEM ((256 * APAD * 4) + 2 * STAGE_B)   // 208896 B

__global__ __launch_bounds__(256) void attn_cp()
{
    extern __shared__ float sm[];
    float (*Qs)[APAD] = (float(*)[APAD])sm;        // [128] fp32 scaled Q
    float (*Ps)[APAD] = Qs + 128;                  // [128] P values
    float* kvf = sm + 256 * APAD;                  // stage planes base (float*)

    const int qb = (int)(gridDim.x - 1) - (int)blockIdx.x;   // big tiles first
    const int bh = blockIdx.y;
    const float* Qp   = g_Q   + (size_t)bh * S_ * DK_;
    const float* Khip = g_Khi + (size_t)bh * S_ * DK_;
    const float* Klop = g_Klo + (size_t)bh * S_ * DK_;
    const float* Vhip = g_Vhi + (size_t)bh * S_ * DK_;   // [d][kv]
    const float* Vlop = g_Vlo + (size_t)bh * S_ * DK_;
    float*       Op   = g_O   + (size_t)bh * S_ * DK_;

    const int tid = threadIdx.x;
    const int wid = tid >> 5;
    const int lane = tid & 31;
    const int g = lane >> 2, t = lane & 3;
    const int wrow = wid * 16;
    const int q0 = qb * 128;
    const int ntiles = 2 * qb + 2;

    const uint32_t kvB = smem_u32(sm) + 256 * APAD * 4;

    // ---- stage Q (scaled by 1/8) ----
    {
        const int r = tid >> 1;
        const int c0 = (tid & 1) * 32;
#pragma unroll
        for (int i = 0; i < 8; i++) {
            float4 q = *(const float4*)&Qp[(size_t)(q0 + r) * DK_ + c0 + 4 * i];
            Qs[r][c0 + 4 * i + 0] = q.x * 0.125f;
            Qs[r][c0 + 4 * i + 1] = q.y * 0.125f;
            Qs[r][c0 + 4 * i + 2] = q.z * 0.125f;
            Qs[r][c0 + 4 * i + 3] = q.w * 0.125f;
        }
    }

    auto issue_stage = [&](int st, int kv0) {
        const uint32_t sb = kvB + (uint32_t)st * STAGE_B;
#pragma unroll
        for (int i = 0; i < 4; i++) {
            const int idx = tid + 256 * i;     // 0..1023
            const int r  = idx >> 4;           // 0..63
            const int c4 = (idx & 15) * 4;     // 0..60
            const uint32_t soff = (uint32_t)(r * APAD + c4) * 4;
            cp16(sb + 0 * PLANE_B + soff, Khip + (size_t)(kv0 + r) * DK_ + c4);
            cp16(sb + 1 * PLANE_B + soff, Klop + (size_t)(kv0 + r) * DK_ + c4);
            cp16(sb + 2 * PLANE_B + soff, Vhip + (size_t)r * S_ + kv0 + c4);
            cp16(sb + 3 * PLANE_B + soff, Vlop + (size_t)r * S_ + kv0 + c4);
        }
    };

    float cO[8][4];
#pragma unroll
    for (int nf = 0; nf < 8; nf++)
#pragma unroll
        for (int q = 0; q < 4; q++) cO[nf][q] = 0.0f;
    float m0v = -1e30f, m1v = -1e30f, l0 = 0.0f, l1 = 0.0f;

    issue_stage(0, 0);
    CP_COMMIT();

    for (int kt = 0; kt < ntiles; kt++) {
        const int kv0 = kt * 64;
        const int st  = kt & 1;

        CP_WAIT(0);
        __syncthreads();

        if (kt + 1 < ntiles) {
            issue_stage(st ^ 1, kv0 + 64);
            CP_COMMIT();
        }

        if (kv0 <= q0 + wrow + 15) {
            const float (*Khi)[APAD] = (const float(*)[APAD])(kvf + st * (STAGE_B / 4));
            const float (*Klo)[APAD] = Khi + 64;
            const float (*Vhi)[APAD] = Klo + 64;
            const float (*Vlo)[APAD] = Vhi + 64;

            float cS[8][4];
#pragma unroll
            for (int nf = 0; nf < 8; nf++)
#pragma unroll
                for (int q = 0; q < 4; q++) cS[nf][q] = 0.0f;

#pragma unroll
            for (int ks = 0; ks < 8; ks++) {
                const int kc = ks * 8;
                uint32_t ah[4], al[4];
                split2(Qs[wrow + g][kc + t],         ah[0], al[0]);
                split2(Qs[wrow + g + 8][kc + t],     ah[1], al[1]);
                split2(Qs[wrow + g][kc + t + 4],     ah[2], al[2]);
                split2(Qs[wrow + g + 8][kc + t + 4], ah[3], al[3]);
#pragma unroll
                for (int nf = 0; nf < 8; nf++) {
                    const uint32_t bh0 = __float_as_uint(Khi[nf * 8 + g][kc + t]);
                    const uint32_t bh1 = __float_as_uint(Khi[nf * 8 + g][kc + t + 4]);
                    const uint32_t bl0 = __float_as_uint(Klo[nf * 8 + g][kc + t]);
                    const uint32_t bl1 = __float_as_uint(Klo[nf * 8 + g][kc + t + 4]);
                    mma8(cS[nf], ah[0], ah[1], ah[2], ah[3], bh0, bh1);
                    mma8(cS[nf], ah[0], ah[1], ah[2], ah[3], bl0, bl1);
                    mma8(cS[nf], al[0], al[1], al[2], al[3], bh0, bh1);
                }
            }

            if (kv0 + 63 > q0 + wrow) {
                const int r0g = q0 + wrow + g;
                const int r1g = r0g + 8;
#pragma unroll
                for (int nf = 0; nf < 8; nf++) {
                    const int col = kv0 + nf * 8 + 2 * t;
                    if (col     > r0g) cS[nf][0] = -1e30f;
                    if (col + 1 > r0g) cS[nf][1] = -1e30f;
                    if (col     > r1g) cS[nf][2] = -1e30f;
                    if (col + 1 > r1g) cS[nf][3] = -1e30f;
                }
            }

            float mx0 = -1e30f, mx1 = -1e30f;
#pragma unroll
            for (int nf = 0; nf < 8; nf++) {
                mx0 = fmaxf(mx0, fmaxf(cS[nf][0], cS[nf][1]));
                mx1 = fmaxf(mx1, fmaxf(cS[nf][2], cS[nf][3]));
            }
            mx0 = fmaxf(mx0, __shfl_xor_sync(0xffffffffu, mx0, 1));
            mx0 = fmaxf(mx0, __shfl_xor_sync(0xffffffffu, mx0, 2));
            mx1 = fmaxf(mx1, __shfl_xor_sync(0xffffffffu, mx1, 1));
            mx1 = fmaxf(mx1, __shfl_xor_sync(0xffffffffu, mx1, 2));
            const float mn0 = fmaxf(m0v, mx0), mn1 = fmaxf(m1v, mx1);
            const float corr0 = __expf(m0v - mn0), corr1 = __expf(m1v - mn1);
            float rs0 = 0.0f, rs1 = 0.0f;
#pragma unroll
            for (int nf = 0; nf < 8; nf++) {
                const float p0 = __expf(cS[nf][0] - mn0);
                const float p1 = __expf(cS[nf][1] - mn0);
                const float p2 = __expf(cS[nf][2] - mn1);
                const float p3 = __expf(cS[nf][3] - mn1);
                rs0 += p0 + p1; rs1 += p2 + p3;
                *(float2*)&Ps[wrow + g][nf * 8 + 2 * t]     = make_float2(p0, p1);
                *(float2*)&Ps[wrow + g + 8][nf * 8 + 2 * t] = make_float2(p2, p3);
            }
            rs0 += __shfl_xor_sync(0xffffffffu, rs0, 1);
            rs0 += __shfl_xor_sync(0xffffffffu, rs0, 2);
            rs1 += __shfl_xor_sync(0xffffffffu, rs1, 1);
            rs1 += __shfl_xor_sync(0xffffffffu, rs1, 2);
            l0 = l0 * corr0 + rs0; l1 = l1 * corr1 + rs1;
            m0v = mn0; m1v = mn1;
#pragma unroll
            for (int nf = 0; nf < 8; nf++) {
                cO[nf][0] *= corr0; cO[nf][1] *= corr0;
                cO[nf][2] *= corr1; cO[nf][3] *= corr1;
            }
            __syncwarp();

#pragma unroll
            for (int ks = 0; ks < 8; ks++) {
                const int kc = ks * 8;
                uint32_t ah[4], al[4];
                split2(Ps[wrow + g][kc + t],         ah[0], al[0]);
                split2(Ps[wrow + g + 8][kc + t],     ah[1], al[1]);
                split2(Ps[wrow + g][kc + t + 4],     ah[2], al[2]);
                split2(Ps[wrow + g + 8][kc + t + 4], ah[3], al[3]);
#pragma unroll
                for (int nf = 0; nf < 8; nf++) {
                    const uint32_t bh0 = __float_as_uint(Vhi[nf * 8 + g][kc + t]);
                    const uint32_t bh1 = __float_as_uint(Vhi[nf * 8 + g][kc + t + 4]);
                    const uint32_t bl0 = __float_as_uint(Vlo[nf * 8 + g][kc + t]);
                    const uint32_t bl1 = __float_as_uint(Vlo[nf * 8 + g][kc + t + 4]);
                    mma8(cO[nf], ah[0], ah[1], ah[2], ah[3], bh0, bh1);
                    mma8(cO[nf], ah[0], ah[1], ah[2], ah[3], bl0, bl1);
                    mma8(cO[nf], al[0], al[1], al[2], al[3], bh0, bh1);
                }
            }
        }
    }

    const float inv0 = 1.0f / l0, inv1 = 1.0f / l1;
#pragma unroll
    for (int nf = 0; nf < 8; nf++) {
        const int col = nf * 8 + 2 * t;
        *(float2*)&Op[(size_t)(q0 + wrow + g) * DK_ + col] =
            make_float2(cO[nf][0] * inv0, cO[nf][1] * inv0);
        *(float2*)&Op[(size_t)(q0 + wrow + g + 8) * DK_ + col] =
            make_float2(cO[nf][2] * inv1, cO[nf][3] * inv1);
    }
}

// ---------------------------------------------------------------------------
extern "C" void kernel_launch(void* const* d_in, const int* in_sizes, int n_in,
                              void* d_out, int out_size)
{
    const float* x  = (const float*)d_in[0];
    const float* Wq = (const float*)d_in[2];
    const float* bq = (const float*)d_in[3];
    const float* Wk = (const float*)d_in[4];
    const float* bk = (const float*)d_in[5];
    const float* Wv = (const float*)d_in[6];
    const float* bv = (const float*)d_in[7];
    const float* Wo = (const float*)d_in[8];
    const float* bo = (const float*)d_in[9];
    float* out = (float*)d_out;

    cudaFuncSetAttribute(qkv_mma, cudaFuncAttributeMaxDynamicSharedMemorySize, GEMM_SMEM);
    cudaFuncSetAttribute(out_mma, cudaFuncAttributeMaxDynamicSharedMemorySize, GEMM_SMEM);
    cudaFuncSetAttribute(attn_cp, cudaFuncAttributeMaxDynamicSharedMemorySize, ATTN_SMEM);

    transpose_qkv<<<dim3(2, 32, 48), dim3(32, 8)>>>(Wq, Wk, Wv);
    transpose_wo<<<dim3(32, 32), dim3(32, 8)>>>(Wo);

    qkv_mma<<<dim3(M_ / 128, D_ / 128, 3), 256, GEMM_SMEM>>>(x, bq, bk, bv);

    attn_cp<<<dim3(S_ / 128, B_ * H_), 256, ATTN_SMEM>>>();

    out_mma<<<dim3(M_ / 128, D_ / 128), 256, GEMM_SMEM>>>(bo, out);
}